// round 2
// baseline (speedup 1.0000x reference)
#include <cuda_runtime.h>
#include <math.h>

#define N_NODES 50000
#define N_EDGES 800000
#define F_IN    11
#define HID     128
#define HEADS   4
#define CDIM    32
#define NLAYERS 4

// ---------------- scratch (device globals; no allocation allowed) ----------
__device__ float g_x [N_NODES * HID];
__device__ float g_xl[N_NODES * HID];
__device__ float g_xr[N_NODES * HID];
__device__ int   g_rowptr[N_NODES + 1];
__device__ int   g_cnt[N_NODES];
__device__ int   g_csr_src[N_EDGES];

// ---------------- embedding: x = relu(nf @ W_emb^T + b_emb) ----------------
__global__ void embed_kernel(const float* __restrict__ nf,
                             const float* __restrict__ Wemb,
                             const float* __restrict__ bemb) {
    int tid = blockIdx.x * blockDim.x + threadIdx.x;
    if (tid >= N_NODES * HID) return;
    int node = tid >> 7;
    int col  = tid & 127;
    const float* xrow = nf + node * F_IN;
    const float* wrow = Wemb + col * F_IN;
    float a = bemb[col];
#pragma unroll
    for (int i = 0; i < F_IN; i++) a += xrow[i] * wrow[i];
    g_x[tid] = fmaxf(a, 0.f);
}

// ---------------- CSR build ------------------------------------------------
__global__ void zero_cnt_kernel() {
    int i = blockIdx.x * blockDim.x + threadIdx.x;
    if (i < N_NODES) g_cnt[i] = 0;
}

__global__ void count_kernel(const int* __restrict__ ei) {
    int e = blockIdx.x * blockDim.x + threadIdx.x;
    if (e < N_EDGES) atomicAdd(&g_cnt[ei[N_EDGES + e]], 1);
}

// single-block scan of 50000 counts -> rowptr (exclusive)
__global__ void scan_kernel() {
    __shared__ int s[1024];
    const int CHUNK = (N_NODES + 1023) / 1024;  // 49
    int t  = threadIdx.x;
    int lo = t * CHUNK;
    int hi = min(lo + CHUNK, N_NODES);
    int local = 0;
    for (int i = lo; i < hi; i++) local += g_cnt[i];
    s[t] = local;
    __syncthreads();
    for (int off = 1; off < 1024; off <<= 1) {
        int v = (t >= off) ? s[t - off] : 0;
        __syncthreads();
        s[t] += v;
        __syncthreads();
    }
    int run = (t == 0) ? 0 : s[t - 1];
    for (int i = lo; i < hi; i++) { g_rowptr[i] = run; run += g_cnt[i]; }
    if (hi == N_NODES) g_rowptr[N_NODES] = run;
}

__global__ void scatter_kernel(const int* __restrict__ ei) {
    int e = blockIdx.x * blockDim.x + threadIdx.x;
    if (e >= N_EDGES) return;
    int src = ei[e];
    int dst = ei[N_EDGES + e];
    int pos = g_rowptr[dst] + atomicAdd(&g_cnt[dst], 1);
    g_csr_src[pos] = src;
}

// ---------------- node transform: xout = g_x @ W^T + b ---------------------
// CTA: 32 nodes x 128 cols. W staged transposed+padded in dyn smem, 4x4 reg tile.
#define WT_STRIDE 132
#define TF_SMEM   ((128 * WT_STRIDE + 32 * 128) * 4)

__global__ __launch_bounds__(256, 2)
void transform_kernel(const float* __restrict__ W,
                      const float* __restrict__ b,
                      int which) {     // 0 -> g_xl, 1 -> g_xr
    extern __shared__ float smem[];
    float* sWt = smem;                      // [128][WT_STRIDE], sWt[k][o] = W[o][k]
    float* sx  = smem + 128 * WT_STRIDE;    // [32][128]
    float* xout = which ? g_xr : g_xl;

    int nbase = blockIdx.x * 32;
    for (int idx = threadIdx.x; idx < 128 * 128; idx += 256) {
        int o = idx >> 7, k = idx & 127;
        sWt[k * WT_STRIDE + o] = W[idx];
    }
    for (int idx = threadIdx.x; idx < 32 * 128; idx += 256) {
        int node = nbase + (idx >> 7);
        sx[idx] = (node < N_NODES) ? g_x[node * HID + (idx & 127)] : 0.f;
    }
    __syncthreads();

    int lane = threadIdx.x & 31;
    int wrp  = threadIdx.x >> 5;
    int col  = lane * 4;
    int nloc = wrp * 4;
    float acc[4][4];
#pragma unroll
    for (int j = 0; j < 4; j++)
#pragma unroll
        for (int i = 0; i < 4; i++) acc[j][i] = 0.f;

#pragma unroll 4
    for (int k = 0; k < 128; k++) {
        float4 wv = *reinterpret_cast<const float4*>(&sWt[k * WT_STRIDE + col]);
#pragma unroll
        for (int j = 0; j < 4; j++) {
            float xv = sx[(nloc + j) * 128 + k];
            acc[j][0] += xv * wv.x;
            acc[j][1] += xv * wv.y;
            acc[j][2] += xv * wv.z;
            acc[j][3] += xv * wv.w;
        }
    }
#pragma unroll
    for (int j = 0; j < 4; j++) {
        int node = nbase + nloc + j;
        if (node < N_NODES) {
            float4 o;
            o.x = acc[j][0] + b[col];
            o.y = acc[j][1] + b[col + 1];
            o.z = acc[j][2] + b[col + 2];
            o.w = acc[j][3] + b[col + 3];
            *reinterpret_cast<float4*>(&g_xl[0] + (xout - g_xl) + node * HID + col) = o;
        }
    }
}

// ---------------- GATv2 aggregation: one warp per destination node ---------
// Online softmax over incoming edges; lane = channel c, 4 heads in registers.
__global__ __launch_bounds__(256)
void gat_agg_kernel(const float* __restrict__ att,
                    const float* __restrict__ bias,
                    int layer) {
    int warp = (blockIdx.x * blockDim.x + threadIdx.x) >> 5;
    int lane = threadIdx.x & 31;
    if (warp >= N_NODES) return;
    int node = warp;

    float xrv[HEADS], attv[HEADS], acc[HEADS], den[HEADS], m[HEADS];
#pragma unroll
    for (int h = 0; h < HEADS; h++) {
        xrv[h]  = g_xr[node * HID + h * CDIM + lane];
        attv[h] = att[layer * HID + h * CDIM + lane];
        acc[h] = 0.f; den[h] = 0.f; m[h] = -1e30f;
    }

    int beg = g_rowptr[node], end = g_rowptr[node + 1];
    for (int i = beg; i < end; i++) {
        int src = g_csr_src[i];
        float xlv[HEADS], lg[HEADS];
#pragma unroll
        for (int h = 0; h < HEADS; h++)
            xlv[h] = g_xl[src * HID + h * CDIM + lane];
#pragma unroll
        for (int h = 0; h < HEADS; h++) {
            float s = xlv[h] + xrv[h];
            s = (s > 0.f) ? s : 0.2f * s;   // leaky_relu
            lg[h] = s * attv[h];
        }
#pragma unroll
        for (int h = 0; h < HEADS; h++) {
#pragma unroll
            for (int off = 16; off > 0; off >>= 1)
                lg[h] += __shfl_xor_sync(0xFFFFFFFFu, lg[h], off);
        }
#pragma unroll
        for (int h = 0; h < HEADS; h++) {
            float l = lg[h];
            if (l > m[h]) {
                float sc = __expf(m[h] - l);
                acc[h] *= sc; den[h] *= sc; m[h] = l;
            }
            float p = __expf(l - m[h]);
            den[h] += p;
            acc[h] += p * xlv[h];
        }
    }

#pragma unroll
    for (int h = 0; h < HEADS; h++) {
        float o = (den[h] > 0.f) ? acc[h] / den[h] : 0.f;
        o += bias[layer * HID + h * CDIM + lane];
        o = fmaxf(o, 0.f);
        if (layer > 0) o += g_x[node * HID + h * CDIM + lane];  // residual
        g_x[node * HID + h * CDIM + lane] = o;
    }
}

// ---------------- epilogue: graph embedding + x ----------------------------
__global__ void zero_out_kernel(float* out) {
    int i = blockIdx.x * blockDim.x + threadIdx.x;
    if (i < 2 * HID) out[i] = 0.f;
}

__global__ void reduce_kernel(float* out) {
    int col = threadIdx.x;   // 128 threads
    float s = 0.f, mx = 0.f;
    for (int r = blockIdx.x; r < N_NODES; r += gridDim.x) {
        float v = g_x[r * HID + col];
        s += v;
        mx = fmaxf(mx, v);
    }
    atomicAdd(&out[col], s * (1.0f / N_NODES));
    atomicMax(reinterpret_cast<int*>(out) + HID + col, __float_as_int(mx));  // x >= 0
}

__global__ void copyx_kernel(float* out) {
    int i = blockIdx.x * blockDim.x + threadIdx.x;
    if (i < N_NODES * HID / 4)
        reinterpret_cast<float4*>(out + 2 * HID)[i] =
            reinterpret_cast<const float4*>(g_x)[i];
}

// ---------------- launch ---------------------------------------------------
extern "C" void kernel_launch(void* const* d_in, const int* in_sizes, int n_in,
                              void* d_out, int out_size) {
    const float* nf   = (const float*)d_in[0];
    const int*   ei   = (const int*)  d_in[1];
    // d_in[2] = num_nodes (unused; compile-time constant)
    const float* Wemb = (const float*)d_in[3];
    const float* bemb = (const float*)d_in[4];
    const float* Wl   = (const float*)d_in[5];
    const float* bl   = (const float*)d_in[6];
    const float* Wr   = (const float*)d_in[7];
    const float* br   = (const float*)d_in[8];
    const float* att  = (const float*)d_in[9];
    const float* bias = (const float*)d_in[10];
    float* out = (float*)d_out;

    cudaFuncSetAttribute(transform_kernel,
                         cudaFuncAttributeMaxDynamicSharedMemorySize, TF_SMEM);

    // embedding
    embed_kernel<<<(N_NODES * HID + 255) / 256, 256>>>(nf, Wemb, bemb);

    // CSR by destination (fixed across layers)
    zero_cnt_kernel<<<(N_NODES + 255) / 256, 256>>>();
    count_kernel<<<(N_EDGES + 255) / 256, 256>>>(ei);
    scan_kernel<<<1, 1024>>>();
    zero_cnt_kernel<<<(N_NODES + 255) / 256, 256>>>();
    scatter_kernel<<<(N_EDGES + 255) / 256, 256>>>(ei);

    // GATv2 layers
    int tf_grid = (N_NODES + 31) / 32;
    for (int l = 0; l < NLAYERS; l++) {
        transform_kernel<<<tf_grid, 256, TF_SMEM>>>(Wl + l * HID * HID, bl + l * HID, 0);
        transform_kernel<<<tf_grid, 256, TF_SMEM>>>(Wr + l * HID * HID, br + l * HID, 1);
        gat_agg_kernel<<<(N_NODES * 32 + 255) / 256, 256>>>(att, bias, l);
    }

    // outputs: [graph_mean(128) | graph_max(128) | x(50000*128)]
    zero_out_kernel<<<1, 256>>>(out);
    reduce_kernel<<<512, HID>>>(out);
    copyx_kernel<<<(N_NODES * HID / 4 + 255) / 256, 256>>>(out);
}

// round 4
// speedup vs baseline: 1.8391x; 1.8391x over previous
#include <cuda_runtime.h>
#include <math.h>

#define N_NODES 50000
#define N_EDGES 800000
#define F_IN    11
#define HID     128
#define HEADS   4
#define CDIM    32
#define NLAYERS 4

// ---------------- scratch (device globals; no allocation allowed) ----------
__device__ float g_x [N_NODES * HID];
__device__ float g_xl[N_NODES * HID];
__device__ float g_xr[N_NODES * HID];
__device__ int   g_rowptr[N_NODES + 1];
__device__ int   g_cnt[N_NODES];
__device__ int   g_csr_src[N_EDGES];

#define SCAN_BLK   512
#define NSCAN_BLKS ((N_NODES + SCAN_BLK - 1) / SCAN_BLK)   // 98
__device__ int g_bsum[NSCAN_BLKS];

// ---------------- f32x2 packed math helpers --------------------------------
__device__ __forceinline__ unsigned long long pack2(float x, float y) {
    unsigned long long r;
    asm("mov.b64 %0, {%1, %2};" : "=l"(r) : "f"(x), "f"(y));
    return r;
}
__device__ __forceinline__ float2 unpack2(unsigned long long v) {
    float2 r;
    asm("mov.b64 {%0, %1}, %2;" : "=f"(r.x), "=f"(r.y) : "l"(v));
    return r;
}
__device__ __forceinline__ void ffma2(unsigned long long& d,
                                      unsigned long long a,
                                      unsigned long long b) {
    asm("fma.rn.f32x2 %0, %1, %2, %0;" : "+l"(d) : "l"(a), "l"(b));
}

// ---------------- embedding: x = relu(nf @ W_emb^T + b_emb) ----------------
__global__ void embed_kernel(const float* __restrict__ nf,
                             const float* __restrict__ Wemb,
                             const float* __restrict__ bemb) {
    int tid = blockIdx.x * blockDim.x + threadIdx.x;
    if (tid >= N_NODES * HID) return;
    int node = tid >> 7;
    int col  = tid & 127;
    const float* xrow = nf + node * F_IN;
    const float* wrow = Wemb + col * F_IN;
    float a = bemb[col];
#pragma unroll
    for (int i = 0; i < F_IN; i++) a += xrow[i] * wrow[i];
    g_x[tid] = fmaxf(a, 0.f);
}

// ---------------- CSR build ------------------------------------------------
__global__ void zero_cnt_out_kernel(float* out) {
    int i = blockIdx.x * blockDim.x + threadIdx.x;
    if (i < N_NODES) g_cnt[i] = 0;
    if (i < 2 * HID) out[i] = 0.f;   // mean accum + max accum (x >= 0)
}

__global__ void zero_cnt_kernel() {
    int i = blockIdx.x * blockDim.x + threadIdx.x;
    if (i < N_NODES) g_cnt[i] = 0;
}

__global__ void count_kernel(const int* __restrict__ ei) {
    int e = blockIdx.x * blockDim.x + threadIdx.x;
    if (e < N_EDGES) atomicAdd(&g_cnt[ei[N_EDGES + e]], 1);
}

__device__ __forceinline__ int warp_incl_scan(int v) {
    int lane = threadIdx.x & 31;
#pragma unroll
    for (int off = 1; off < 32; off <<= 1) {
        int n = __shfl_up_sync(0xFFFFFFFFu, v, off);
        if (lane >= off) v += n;
    }
    return v;
}

__global__ void blocksum_kernel() {
    __shared__ int ws[SCAN_BLK / 32];
    int i = blockIdx.x * SCAN_BLK + threadIdx.x;
    int v = (i < N_NODES) ? g_cnt[i] : 0;
#pragma unroll
    for (int off = 16; off > 0; off >>= 1) v += __shfl_xor_sync(0xFFFFFFFFu, v, off);
    if ((threadIdx.x & 31) == 0) ws[threadIdx.x >> 5] = v;
    __syncthreads();
    if (threadIdx.x < 32) {
        int t = (threadIdx.x < SCAN_BLK / 32) ? ws[threadIdx.x] : 0;
#pragma unroll
        for (int off = 8; off > 0; off >>= 1) t += __shfl_xor_sync(0xFFFFFFFFu, t, off);
        if (threadIdx.x == 0) g_bsum[blockIdx.x] = t;
    }
}

__global__ void bsum_scan_kernel() {   // 1 block, 128 threads, scans 98 values
    __shared__ int ws[4];
    int tid = threadIdx.x;
    int v = (tid < NSCAN_BLKS) ? g_bsum[tid] : 0;
    int incl = warp_incl_scan(v);
    if ((tid & 31) == 31) ws[tid >> 5] = incl;
    __syncthreads();
    if (tid < 32) {
        int t = (tid < 4) ? ws[tid] : 0;
        t = warp_incl_scan(t);
        if (tid < 4) ws[tid] = t;
    }
    __syncthreads();
    int wid = tid >> 5;
    int excl = (wid ? ws[wid - 1] : 0) + incl - v;
    if (tid < NSCAN_BLKS) g_bsum[tid] = excl;
}

__global__ void rowptr_kernel() {
    __shared__ int ws[SCAN_BLK / 32];
    int tid = threadIdx.x;
    int i = blockIdx.x * SCAN_BLK + tid;
    int v = (i < N_NODES) ? g_cnt[i] : 0;
    int incl = warp_incl_scan(v);
    int wid = tid >> 5;
    if ((tid & 31) == 31) ws[wid] = incl;
    __syncthreads();
    if (tid < 32) {
        int t = (tid < SCAN_BLK / 32) ? ws[tid] : 0;
        t = warp_incl_scan(t);
        if (tid < SCAN_BLK / 32) ws[tid] = t;
    }
    __syncthreads();
    int base = g_bsum[blockIdx.x] + (wid ? ws[wid - 1] : 0);
    int excl = base + incl - v;
    if (i < N_NODES)      g_rowptr[i] = excl;
    if (i == N_NODES - 1) g_rowptr[N_NODES] = excl + v;
}

__global__ void scatter_kernel(const int* __restrict__ ei) {
    int e = blockIdx.x * blockDim.x + threadIdx.x;
    if (e >= N_EDGES) return;
    int src = ei[e];
    int dst = ei[N_EDGES + e];
    int pos = g_rowptr[dst] + atomicAdd(&g_cnt[dst], 1);
    g_csr_src[pos] = src;
}

// ---------------- fused node transform: xl = x@Wl^T+bl, xr = x@Wr^T+br -----
// CTA: 64 nodes x 128 cols, 256 threads (8 warps x 8 nodes each).
// Weights transposed+padded in smem; packed f32x2 FMA accumulators.
#define BN        64
#define WT_STRIDE 132
#define TF_SMEM   ((128 * WT_STRIDE * 2 + BN * HID) * 4)

__global__ __launch_bounds__(256, 1)
void transform_fused_kernel(const float* __restrict__ Wlg,
                            const float* __restrict__ blg,
                            const float* __restrict__ Wrg,
                            const float* __restrict__ brg) {
    extern __shared__ float smem[];
    float* sWl = smem;                          // [128][WT_STRIDE]  sWl[k][o]
    float* sWr = smem + 128 * WT_STRIDE;
    float* sx  = smem + 2 * 128 * WT_STRIDE;    // [BN][128]

    int nbase = blockIdx.x * BN;
    for (int idx = threadIdx.x; idx < HID * HID; idx += 256) {
        int o = idx >> 7, k = idx & 127;
        sWl[k * WT_STRIDE + o] = Wlg[idx];
        sWr[k * WT_STRIDE + o] = Wrg[idx];
    }
    for (int idx = threadIdx.x; idx < BN * HID; idx += 256) {
        int node = nbase + (idx >> 7);
        sx[idx] = (node < N_NODES) ? g_x[node * HID + (idx & 127)] : 0.f;
    }
    __syncthreads();

    int lane = threadIdx.x & 31;
    int wrp  = threadIdx.x >> 5;
    int col  = lane * 4;
    int n0   = wrp * 8;

    unsigned long long accL[8][2], accR[8][2];
#pragma unroll
    for (int j = 0; j < 8; j++) {
        accL[j][0] = 0ull; accL[j][1] = 0ull;
        accR[j][0] = 0ull; accR[j][1] = 0ull;
    }

    for (int kq = 0; kq < 128; kq += 4) {
        float4 xq[8];
#pragma unroll
        for (int j = 0; j < 8; j++)
            xq[j] = *reinterpret_cast<const float4*>(&sx[(n0 + j) * HID + kq]);
        const float* xs = reinterpret_cast<const float*>(xq);
#pragma unroll
        for (int kk = 0; kk < 4; kk++) {
            int k = kq + kk;
            ulonglong2 wl = *reinterpret_cast<const ulonglong2*>(&sWl[k * WT_STRIDE + col]);
            ulonglong2 wr = *reinterpret_cast<const ulonglong2*>(&sWr[k * WT_STRIDE + col]);
#pragma unroll
            for (int j = 0; j < 8; j++) {
                float xv = xs[j * 4 + kk];
                unsigned long long xp = pack2(xv, xv);
                ffma2(accL[j][0], xp, wl.x);
                ffma2(accL[j][1], xp, wl.y);
                ffma2(accR[j][0], xp, wr.x);
                ffma2(accR[j][1], xp, wr.y);
            }
        }
    }

    float4 bl4 = *reinterpret_cast<const float4*>(&blg[col]);
    float4 br4 = *reinterpret_cast<const float4*>(&brg[col]);
#pragma unroll
    for (int j = 0; j < 8; j++) {
        int node = nbase + n0 + j;
        if (node < N_NODES) {
            float2 l0 = unpack2(accL[j][0]), l1 = unpack2(accL[j][1]);
            float2 r0 = unpack2(accR[j][0]), r1 = unpack2(accR[j][1]);
            float4 ol = {l0.x + bl4.x, l0.y + bl4.y, l1.x + bl4.z, l1.y + bl4.w};
            float4 orr = {r0.x + br4.x, r0.y + br4.y, r1.x + br4.z, r1.y + br4.w};
            *reinterpret_cast<float4*>(&g_xl[node * HID + col]) = ol;
            *reinterpret_cast<float4*>(&g_xr[node * HID + col]) = orr;
        }
    }
}

// ---------------- GATv2 aggregation: one warp per destination node ---------
// lane = h*8 + i; lane owns channels [h*32 + i*4 .. +3] as float4.
// 3 shfl per edge for all heads; branchless online softmax; src prefetch.
__global__ __launch_bounds__(256)
void gat_agg_kernel(const float* __restrict__ att,
                    const float* __restrict__ bias,
                    int layer) {
    int warp = (blockIdx.x * blockDim.x + threadIdx.x) >> 5;
    int lane = threadIdx.x & 31;
    if (warp >= N_NODES) return;
    int node = warp;
    int h = lane >> 3;
    int i4 = (lane & 7) * 4;
    int chan = h * CDIM + i4;
    int base = node * HID + chan;

    float4 xr4 = *reinterpret_cast<const float4*>(&g_xr[base]);
    float4 at4 = *reinterpret_cast<const float4*>(&att[layer * HID + chan]);

    float4 acc = {0.f, 0.f, 0.f, 0.f};
    float den = 0.f, m = -1e30f;

    int beg = g_rowptr[node], end = g_rowptr[node + 1];
    if (beg < end) {
        int src = g_csr_src[beg];
        float4 xl4 = *reinterpret_cast<const float4*>(&g_xl[src * HID + chan]);
        for (int e = beg; e < end; e++) {
            // prefetch next edge while current one is processed
            float4 nxt;
            if (e + 1 < end) {
                int nsrc = g_csr_src[e + 1];
                nxt = *reinterpret_cast<const float4*>(&g_xl[nsrc * HID + chan]);
            }
            float s0 = xl4.x + xr4.x, s1 = xl4.y + xr4.y;
            float s2 = xl4.z + xr4.z, s3 = xl4.w + xr4.w;
            s0 = (s0 > 0.f) ? s0 : 0.2f * s0;
            s1 = (s1 > 0.f) ? s1 : 0.2f * s1;
            s2 = (s2 > 0.f) ? s2 : 0.2f * s2;
            s3 = (s3 > 0.f) ? s3 : 0.2f * s3;
            float part = s0 * at4.x + s1 * at4.y + s2 * at4.z + s3 * at4.w;
            part += __shfl_xor_sync(0xFFFFFFFFu, part, 4);
            part += __shfl_xor_sync(0xFFFFFFFFu, part, 2);
            part += __shfl_xor_sync(0xFFFFFFFFu, part, 1);
            float l = part;
            float nm = fmaxf(m, l);
            float sc = __expf(m - nm);
            float p  = __expf(l - nm);
            den = den * sc + p;
            acc.x = acc.x * sc + p * xl4.x;
            acc.y = acc.y * sc + p * xl4.y;
            acc.z = acc.z * sc + p * xl4.z;
            acc.w = acc.w * sc + p * xl4.w;
            m = nm;
            xl4 = nxt;
        }
    }

    float inv = (den > 0.f) ? 1.f / den : 0.f;
    float4 b4 = *reinterpret_cast<const float4*>(&bias[layer * HID + chan]);
    float4 o;
    o.x = fmaxf(acc.x * inv + b4.x, 0.f);
    o.y = fmaxf(acc.y * inv + b4.y, 0.f);
    o.z = fmaxf(acc.z * inv + b4.z, 0.f);
    o.w = fmaxf(acc.w * inv + b4.w, 0.f);
    if (layer > 0) {
        float4 prev = *reinterpret_cast<const float4*>(&g_x[base]);
        o.x += prev.x; o.y += prev.y; o.z += prev.z; o.w += prev.w;
    }
    *reinterpret_cast<float4*>(&g_x[base]) = o;
}

// ---------------- epilogue: graph embedding + x copy (fused) ---------------
__global__ void reduce2_kernel(float* __restrict__ out) {
    int col = threadIdx.x;   // 128 threads
    float s = 0.f, mx = 0.f;
    for (int r = blockIdx.x; r < N_NODES; r += gridDim.x) {
        float v = g_x[r * HID + col];
        s += v;
        mx = fmaxf(mx, v);
        out[2 * HID + r * HID + col] = v;
    }
    atomicAdd(&out[col], s * (1.0f / N_NODES));
    atomicMax(reinterpret_cast<int*>(out) + HID + col, __float_as_int(mx));  // x >= 0
}

// ---------------- launch ---------------------------------------------------
extern "C" void kernel_launch(void* const* d_in, const int* in_sizes, int n_in,
                              void* d_out, int out_size) {
    const float* nf   = (const float*)d_in[0];
    const int*   ei   = (const int*)  d_in[1];
    const float* Wemb = (const float*)d_in[3];
    const float* bemb = (const float*)d_in[4];
    const float* Wl   = (const float*)d_in[5];
    const float* bl   = (const float*)d_in[6];
    const float* Wr   = (const float*)d_in[7];
    const float* br   = (const float*)d_in[8];
    const float* att  = (const float*)d_in[9];
    const float* bias = (const float*)d_in[10];
    float* out = (float*)d_out;

    cudaFuncSetAttribute(transform_fused_kernel,
                         cudaFuncAttributeMaxDynamicSharedMemorySize, TF_SMEM);

    // embedding
    embed_kernel<<<(N_NODES * HID + 255) / 256, 256>>>(nf, Wemb, bemb);

    // CSR by destination
    zero_cnt_out_kernel<<<(N_NODES + 255) / 256, 256>>>(out);
    count_kernel<<<(N_EDGES + 255) / 256, 256>>>(ei);
    blocksum_kernel<<<NSCAN_BLKS, SCAN_BLK>>>();
    bsum_scan_kernel<<<1, 128>>>();
    rowptr_kernel<<<NSCAN_BLKS, SCAN_BLK>>>();
    zero_cnt_kernel<<<(N_NODES + 255) / 256, 256>>>();
    scatter_kernel<<<(N_EDGES + 255) / 256, 256>>>(ei);

    // GATv2 layers
    int tf_grid = (N_NODES + BN - 1) / BN;
    for (int l = 0; l < NLAYERS; l++) {
        transform_fused_kernel<<<tf_grid, 256, TF_SMEM>>>(
            Wl + l * HID * HID, bl + l * HID, Wr + l * HID * HID, br + l * HID);
        gat_agg_kernel<<<(N_NODES * 32 + 255) / 256, 256>>>(att, bias, l);
    }

    // outputs: [graph_mean(128) | graph_max(128) | x(50000*128)]
    reduce2_kernel<<<1024, HID>>>(out);
}